// round 2
// baseline (speedup 1.0000x reference)
#include <cuda_runtime.h>
#include <math.h>

#define BB 4
#define VV 8192
#define FF 16384
#define NN 8192
#define SS 8                       // F-chunks per batch for grid parallelism
#define CHUNK (FF / SS)            // 2048 faces per block
#define TILE 1024                  // faces staged in smem per stage (16 KB)
#define SCAN_THREADS 128
#define PT 4                       // points per thread
#define PTS_PER_BLOCK (SCAN_THREADS * PT)   // 512
#define EPS_C 1e-3f
#define WEIGHT_C 1000.0

// ---- scratch (no allocations allowed) ----
__device__ float4 g_c4[BB * FF];        // (cx, cy, cz, |c|^2)
__device__ float4 g_nrm[BB * FF];       // unit normal
__device__ float  g_pscore[BB * SS * NN];
__device__ int    g_pidx[BB * SS * NN];
__device__ double g_acc[2];             // [0]=sum interp^3, [1]=count(interp>0)

__global__ void init_kernel() {
    g_acc[0] = 0.0;
    g_acc[1] = 0.0;
}

// One thread per face: center, |center|^2, unit normal.
__global__ void faces_kernel(const float* __restrict__ opos,
                             const int* __restrict__ faces) {
    int t = blockIdx.x * blockDim.x + threadIdx.x;
    if (t >= BB * FF) return;
    int b = t / FF;
    const int* fp = faces + (size_t)t * 3;
    int i0 = fp[0], i1 = fp[1], i2 = fp[2];
    const float* pb = opos + (size_t)b * VV * 3;

    float x0 = __ldg(pb + i0 * 3 + 0), y0 = __ldg(pb + i0 * 3 + 1), z0 = __ldg(pb + i0 * 3 + 2);
    float x1 = __ldg(pb + i1 * 3 + 0), y1 = __ldg(pb + i1 * 3 + 1), z1 = __ldg(pb + i1 * 3 + 2);
    float x2 = __ldg(pb + i2 * 3 + 0), y2 = __ldg(pb + i2 * 3 + 1), z2 = __ldg(pb + i2 * 3 + 2);

    const float third = 1.0f / 3.0f;
    float cx = (x0 + x1 + x2) * third;
    float cy = (y0 + y1 + y2) * third;
    float cz = (z0 + z1 + z2) * third;

    float e1x = x1 - x0, e1y = y1 - y0, e1z = z1 - z0;
    float e2x = x2 - x0, e2y = y2 - y0, e2z = z2 - z0;
    float nx = e1y * e2z - e1z * e2y;
    float ny = e1z * e2x - e1x * e2z;
    float nz = e1x * e2y - e1y * e2x;
    float len = sqrtf(nx * nx + ny * ny + nz * nz);
    float inv = 1.0f / fmaxf(len, 1e-12f);

    g_c4[t]  = make_float4(cx, cy, cz, cx * cx + cy * cy + cz * cz);
    g_nrm[t] = make_float4(nx * inv, ny * inv, nz * inv, 0.0f);
}

// Each block: 512 points x 2048-face chunk. Partial argmin with first-index
// tie-breaking (strict < over ascending face index).
__global__ __launch_bounds__(SCAN_THREADS)
void scan_kernel(const float* __restrict__ pred) {
    __shared__ float4 tile[TILE];
    int b = blockIdx.z;
    int s = blockIdx.y;
    int pbase = blockIdx.x * PTS_PER_BLOCK;
    int tid = threadIdx.x;

    float qx[PT], qy[PT], qz[PT], best[PT];
    int bidx[PT], npt[PT];
#pragma unroll
    for (int k = 0; k < PT; k++) {
        int n = pbase + k * SCAN_THREADS + tid;
        npt[k] = n;
        const float* pp = pred + ((size_t)b * NN + n) * 3;
        qx[k] = -2.0f * __ldg(pp + 0);
        qy[k] = -2.0f * __ldg(pp + 1);
        qz[k] = -2.0f * __ldg(pp + 2);
        best[k] = 3.4e38f;
        bidx[k] = 0;
    }

    int fbase = s * CHUNK;
    const float4* cbase = g_c4 + (size_t)b * FF + fbase;

    for (int t0 = 0; t0 < CHUNK; t0 += TILE) {
        for (int i = tid; i < TILE; i += SCAN_THREADS)
            tile[i] = cbase[t0 + i];
        __syncthreads();

#pragma unroll 8
        for (int j = 0; j < TILE; j++) {
            float4 c = tile[j];
#pragma unroll
            for (int k = 0; k < PT; k++) {
                float sc = fmaf(qx[k], c.x,
                           fmaf(qy[k], c.y,
                           fmaf(qz[k], c.z, c.w)));
                if (sc < best[k]) { best[k] = sc; bidx[k] = fbase + t0 + j; }
            }
        }
        __syncthreads();
    }

    size_t obase = ((size_t)(b * SS + s)) * NN;
#pragma unroll
    for (int k = 0; k < PT; k++) {
        g_pscore[obase + npt[k]] = best[k];
        g_pidx[obase + npt[k]]   = bidx[k];
    }
}

// Merge chunk partials (ascending chunk order preserves argmin tie-break),
// compute signed distance + hinge, reduce to double accumulators.
__global__ __launch_bounds__(256)
void reduce_kernel(const float* __restrict__ pred) {
    __shared__ double s_loss[256];
    __shared__ double s_cnt[256];

    int t = blockIdx.x * blockDim.x + threadIdx.x;   // [0, BB*NN)
    int b = t / NN;
    int n = t % NN;

    float best = 3.4e38f;
    int bidx = 0;
#pragma unroll
    for (int s = 0; s < SS; s++) {
        size_t o = ((size_t)(b * SS + s)) * NN + n;
        float sc = g_pscore[o];
        int   id = g_pidx[o];
        if (sc < best) { best = sc; bidx = id; }
    }

    float4 c  = g_c4[(size_t)b * FF + bidx];
    float4 nr = g_nrm[(size_t)b * FF + bidx];
    const float* pp = pred + (size_t)t * 3;
    float px = __ldg(pp + 0), py = __ldg(pp + 1), pz = __ldg(pp + 2);
    float d = (px - c.x) * nr.x + (py - c.y) * nr.y + (pz - c.z) * nr.z;
    float interp = fmaxf(EPS_C - d, 0.0f);

    s_loss[threadIdx.x] = (double)(interp * interp * interp);
    s_cnt[threadIdx.x]  = (interp > 0.0f) ? 1.0 : 0.0;
    __syncthreads();

    for (int stride = 128; stride > 0; stride >>= 1) {
        if (threadIdx.x < stride) {
            s_loss[threadIdx.x] += s_loss[threadIdx.x + stride];
            s_cnt[threadIdx.x]  += s_cnt[threadIdx.x + stride];
        }
        __syncthreads();
    }
    if (threadIdx.x == 0) {
        atomicAdd(&g_acc[0], s_loss[0]);
        atomicAdd(&g_acc[1], s_cnt[0]);
    }
}

__global__ void finalize_kernel(float* __restrict__ out) {
    out[0] = (float)(g_acc[0] / (double)BB * WEIGHT_C);
    out[1] = (float)(g_acc[1] / (double)(BB * NN));
}

extern "C" void kernel_launch(void* const* d_in, const int* in_sizes, int n_in,
                              void* d_out, int out_size) {
    const float* pred  = (const float*)d_in[0];   // [B,N,3] f32
    const float* opos  = (const float*)d_in[1];   // [B,V,3] f32
    const int*   faces = (const int*)d_in[2];     // [B,F,3] i32
    float* out = (float*)d_out;

    init_kernel<<<1, 1>>>();
    faces_kernel<<<(BB * FF + 255) / 256, 256>>>(opos, faces);
    scan_kernel<<<dim3(NN / PTS_PER_BLOCK, SS, BB), SCAN_THREADS>>>(pred);
    reduce_kernel<<<(BB * NN) / 256, 256>>>(pred);
    finalize_kernel<<<1, 1>>>(out);
}